// round 14
// baseline (speedup 1.0000x reference)
#include <cuda_runtime.h>
#include <cuda_fp16.h>
#include <cuda.h>
#include <dlfcn.h>
#include <cstdint>
#include <cstddef>

// ---------------------------------------------------------------------------
// Problem dims (fixed by the dataset)
// ---------------------------------------------------------------------------
#define B_DIM 16384
#define C_DIM 1000
#define D_DIM 1024
#define CPAD  1024   // padded K / leading dim everywhere

// GEMM tiling (fp16 m16n8k16): 128x128x64 CTA tile, 4 warps of 64x64, occ 2
#define BM 128
#define BN 128
#define BK 64              // fp16 elements per k-tile = 128 B per row
#define KT 16              // k-steps per tile (CPAD / BK)
#define STAGES 3
#define NTH 128
#define NTILES_M (B_DIM / BM)     // 128
#define NTILES_N 8                // ceil(1000/128)
#define NTILES (NTILES_M * NTILES_N)  // 1024
#define GRID 296                  // 2 persistent CTAs per SM x 148 SMs

#define A_TILE_BYTES (BM * 128)                 // 16384 (swizzled 128B rows)
#define B_TILE_BYTES (BN * 128)                 // 16384
#define STAGE_BYTES (A_TILE_BYTES + B_TILE_BYTES)   // 32768
#define TX_BYTES STAGE_BYTES                    // exact TMA bytes per stage
#define SMEM_BYTES (STAGES * STAGE_BYTES + 1024)    // +align slack -> 2 CTAs/SM

// ---------------------------------------------------------------------------
// Device scratch (no allocation allowed). Zero-initialized at load.
// ---------------------------------------------------------------------------
__device__ __half g_xh   [(size_t)B_DIM * CPAD];   // fp16(x)
__device__ __half g_wph  [(size_t)C_DIM * CPAD];   // fp16(Wp)
__device__ __half g_adj1 [(size_t)C_DIM * CPAD];   // fp16(adj*w1)
__device__ __half g_adj2 [(size_t)C_DIM * CPAD];
__device__ __half g_xinit_h[(size_t)B_DIM * CPAD]; // fp16(x@Wp^T+bp)
__device__ float  g_xinit_f[(size_t)B_DIM * CPAD]; // f32 copy for residual
__device__ __half g_out1_h [(size_t)B_DIM * CPAD]; // fp16(relu(gcn1))

// ---------------------------------------------------------------------------
// PTX helpers (sm_80/sm_90 base features only — legal for plain sm_100)
// ---------------------------------------------------------------------------
__device__ __forceinline__ uint32_t su32(const void* p) {
    uint32_t a;
    asm("{ .reg .u64 t; cvta.to.shared.u64 t, %1; cvt.u32.u64 %0, t; }"
        : "=r"(a) : "l"(p));
    return a;
}

#define MBAR_INIT(addr, cnt) \
    asm volatile("mbarrier.init.shared.b64 [%0], %1;" \
                 :: "r"(addr), "r"((uint32_t)(cnt)) : "memory")
#define MBAR_EXPECT(addr, bytes) \
    asm volatile("mbarrier.arrive.expect_tx.shared::cta.b64 _, [%0], %1;" \
                 :: "r"(addr), "r"((uint32_t)(bytes)) : "memory")

__device__ __forceinline__ void mbar_wait(uint32_t mbar, uint32_t parity) {
    uint32_t done;
    asm volatile(
        "{ .reg .pred p;\n"
        "  mbarrier.try_wait.parity.acquire.cta.shared::cta.b64 p, [%1], %2;\n"
        "  selp.b32 %0, 1, 0, p; }"
        : "=r"(done) : "r"(mbar), "r"(parity) : "memory");
    if (!done) {
        asm volatile(
            "{ .reg .pred P1;\n"
            "WAIT_LOOP_%=:\n"
            "  mbarrier.try_wait.parity.acquire.cta.shared::cta.b64 P1, [%0], %1, 0x989680;\n"
            "  @P1 bra.uni WAIT_DONE_%=;\n"
            "  bra.uni WAIT_LOOP_%=;\n"
            "WAIT_DONE_%=:\n}"
            :: "r"(mbar), "r"(parity) : "memory");
    }
}

__device__ __forceinline__ void tma2d(uint32_t dst, const void* map,
                                      int x, int y, uint32_t mbar) {
    asm volatile(
        "cp.async.bulk.tensor.2d.shared::cta.global.tile.mbarrier::complete_tx::bytes "
        "[%0], [%1, {%2, %3}], [%4];"
        :: "r"(dst), "l"(map), "r"(x), "r"(y), "r"(mbar) : "memory");
}

__device__ __forceinline__ void ldsm4(uint32_t* r, uint32_t addr) {
    asm volatile("ldmatrix.sync.aligned.m8n8.x4.shared.b16 {%0,%1,%2,%3}, [%4];"
                 : "=r"(r[0]), "=r"(r[1]), "=r"(r[2]), "=r"(r[3])
                 : "r"(addr));
}

__device__ __forceinline__ void mma16816(float* c, const uint32_t* a,
                                         uint32_t b0, uint32_t b1) {
    asm volatile(
        "mma.sync.aligned.m16n8k16.row.col.f32.f16.f16.f32 "
        "{%0,%1,%2,%3}, {%4,%5,%6,%7}, {%8,%9}, {%0,%1,%2,%3};\n"
        : "+f"(c[0]), "+f"(c[1]), "+f"(c[2]), "+f"(c[3])
        : "r"(a[0]), "r"(a[1]), "r"(a[2]), "r"(a[3]), "r"(b0), "r"(b1));
}

// ---------------------------------------------------------------------------
// Prep kernels
// ---------------------------------------------------------------------------
__global__ void conv_half_kernel(const float* __restrict__ src,
                                 __half* __restrict__ dst, int n4) {
    int i = blockIdx.x * blockDim.x + threadIdx.x;
    if (i < n4) {
        float4 v = reinterpret_cast<const float4*>(src)[i];
        __half2 h0 = __floats2half2_rn(v.x, v.y);
        __half2 h1 = __floats2half2_rn(v.z, v.w);
        uint2 u;
        u.x = *reinterpret_cast<uint32_t*>(&h0);
        u.y = *reinterpret_cast<uint32_t*>(&h1);
        reinterpret_cast<uint2*>(dst)[i] = u;
    }
}

__global__ void prep_adj_kernel(const float* __restrict__ adj,
                                const float* __restrict__ hw1,
                                const float* __restrict__ hw2) {
    int k = blockIdx.x * blockDim.x + threadIdx.x;   // 0..1023
    int c = blockIdx.y;                              // 0..999
    float a1 = 0.f, a2 = 0.f;
    if (k < C_DIM) {
        float av = adj[(size_t)c * C_DIM + k];
        float w1 = (hw1[k] + hw1[C_DIM + k] + hw1[2 * C_DIM + k]) * (1.f / 3.f);
        float w2 = (hw2[k] + hw2[C_DIM + k] + hw2[2 * C_DIM + k]) * (1.f / 3.f);
        a1 = av * w1;
        a2 = av * w2;
    }
    g_adj1[(size_t)c * CPAD + k] = __float2half_rn(a1);
    g_adj2[(size_t)c * CPAD + k] = __float2half_rn(a2);
}

// ---------------------------------------------------------------------------
// Persistent fused fp16 mma.sync GEMM, TMA + flat cross-tile pipeline
// (128x128x64 tiles, 64x64 warp tiles, 4 warps, occ 2, R12 sync scheme)
//   MODE 0: +bias -> fp16 CoutH AND f32 CoutF       (ld CPAD)
//   MODE 1: relu  -> fp16 CoutH                     (ld CPAD)
//   MODE 2: CoutF = resid + 0.5*acc                 (ld C_DIM, final output)
// tile id tt: m0 = (tt>>3)*BM, n0 = (tt&7)*BN. CTA bid owns tt = bid + k*G.
// ---------------------------------------------------------------------------
template <int MODE>
__global__ void __launch_bounds__(NTH, 2)
gemm_tc(const __grid_constant__ CUtensorMap tmA,
        const __grid_constant__ CUtensorMap tmB,
        const float* __restrict__ bias, const float* __restrict__ resid,
        float* __restrict__ CoutF, __half* __restrict__ CoutH)
{
    extern __shared__ char smem[];
    const uint32_t sraw = su32(smem);
    const uint32_t sm0 = (sraw + 1023u) & ~1023u;   // 1024-align for SW128
    __shared__ __align__(8) uint64_t mbar_s[STAGES];
    const uint32_t mb0 = su32(mbar_s);

    const int tid  = threadIdx.x;
    const int warp = tid >> 5;
    const int lane = tid & 31;
    const int g = lane >> 2;          // groupID 0..7
    const int t = lane & 3;           // thread-in-group 0..3
    const int wm = (warp >> 1) * 64;  // warp M offset (0 or 64)
    const int wn = (warp & 1) * 64;   // warp N offset (0 or 64)

    const int bid = blockIdx.x;
    const int G   = gridDim.x;
    const int my_ntiles = (NTILES - bid + G - 1) / G;
    const int S = my_ntiles * KT;     // flat step count (uniform within CTA)

    if (tid == 0) {
#pragma unroll
        for (int s = 0; s < STAGES; s++) MBAR_INIT(mb0 + 8u * s, 1);
    }
    __syncthreads();

    // producer lambda: issue step sp into slot sp%3
    auto issue = [&](int sp) {
        const int tt = bid + (sp >> 4) * G;       // sp/KT
        const int sl = sp % STAGES;
        const uint32_t mb = mb0 + 8u * sl;
        MBAR_EXPECT(mb, TX_BYTES);
        const int xk = (sp & (KT - 1)) * BK;
        tma2d(sm0 + sl * STAGE_BYTES, &tmA, xk, (tt >> 3) * BM, mb);
        tma2d(sm0 + sl * STAGE_BYTES + A_TILE_BYTES, &tmB, xk, (tt & 7) * BN, mb);
    };

    // prologue: steps 0,1 (slots fresh, no reuse guard needed)
    if (tid == 0) {
        if (0 < S) issue(0);
        if (1 < S) issue(1);
    }

    // ldmatrix per-thread row addressing: matrix id = lane>>3, row = lane&7.
    const int mi  = lane >> 3;
    const int rid = lane & 7;
    const int aRow = wm + (mi & 1) * 8 + rid;       // + i*16
    const int aKh  = mi >> 1;                       // k-half within k16
    const int bRow = wn + (mi >> 1) * 8 + rid;      // + jj*16
    const int bKh  = mi & 1;

    float acc[4][8][4];
#pragma unroll
    for (int i = 0; i < 4; i++)
#pragma unroll
        for (int j = 0; j < 8; j++)
#pragma unroll
            for (int c = 0; c < 4; c++) acc[i][j][c] = 0.f;

    for (int s = 0; s < S; s++) {
        const int slot = s % STAGES;
        mbar_wait(mb0 + 8u * slot, (uint32_t)((s / STAGES) & 1));
        __syncthreads();   // all threads done reading step s-1 (slot (s+2)%3)

        if (tid == 0 && s + 2 < S) issue(s + 2);

        const uint32_t sA = sm0 + slot * STAGE_BYTES;
        const uint32_t sB = sA + A_TILE_BYTES;

#pragma unroll
        for (int ks = 0; ks < 4; ks++) {           // 4 x k16 steps per 64-k tile
            const int ga = 2 * ks + aKh;           // A swizzle granule
            const int gb = 2 * ks + bKh;           // B swizzle granule
            uint32_t a[4][4], b[4][4];
#pragma unroll
            for (int i = 0; i < 4; i++) {
                const int r = aRow + i * 16;
                ldsm4(a[i], sA + (uint32_t)(r * 128 + ((ga ^ (r & 7)) << 4)));
            }
#pragma unroll
            for (int jj = 0; jj < 4; jj++) {
                const int r = bRow + jj * 16;
                ldsm4(b[jj], sB + (uint32_t)(r * 128 + ((gb ^ (r & 7)) << 4)));
            }
#pragma unroll
            for (int i = 0; i < 4; i++)
#pragma unroll
                for (int j = 0; j < 8; j++)
                    mma16816(acc[i][j], a[i],
                             b[j >> 1][(j & 1) * 2], b[j >> 1][(j & 1) * 2 + 1]);
        }

        // tile boundary: epilogue + acc reset (overlaps in-flight TMA loads)
        if ((s & (KT - 1)) == KT - 1) {
            const int tt = bid + (s >> 4) * G;
            const int m0 = (tt >> 3) * BM;
            const int n0 = (tt & 7) * BN;
#pragma unroll
            for (int i = 0; i < 4; i++) {
                const int mr0 = m0 + wm + i * 16 + g;   // rows mr0, mr0+8
#pragma unroll
                for (int j = 0; j < 8; j++) {
                    const int n = n0 + wn + j * 8 + t * 2;
                    if (n < C_DIM) {
                        float c0 = acc[i][j][0], c1 = acc[i][j][1];
                        float c2 = acc[i][j][2], c3 = acc[i][j][3];
                        if (MODE == 0) {
                            const float b0 = bias[n], b1 = bias[n + 1];
                            c0 += b0; c1 += b1; c2 += b0; c3 += b1;
                            __half2 h0 = __floats2half2_rn(c0, c1);
                            __half2 h1 = __floats2half2_rn(c2, c3);
                            *reinterpret_cast<__half2*>(
                                CoutH + (size_t)mr0 * CPAD + n) = h0;
                            *reinterpret_cast<__half2*>(
                                CoutH + (size_t)(mr0 + 8) * CPAD + n) = h1;
                            *reinterpret_cast<float2*>(
                                CoutF + (size_t)mr0 * CPAD + n) =
                                make_float2(c0, c1);
                            *reinterpret_cast<float2*>(
                                CoutF + (size_t)(mr0 + 8) * CPAD + n) =
                                make_float2(c2, c3);
                        } else if (MODE == 1) {
                            c0 = fmaxf(c0, 0.f); c1 = fmaxf(c1, 0.f);
                            c2 = fmaxf(c2, 0.f); c3 = fmaxf(c3, 0.f);
                            __half2 h0 = __floats2half2_rn(c0, c1);
                            __half2 h1 = __floats2half2_rn(c2, c3);
                            *reinterpret_cast<__half2*>(
                                CoutH + (size_t)mr0 * CPAD + n) = h0;
                            *reinterpret_cast<__half2*>(
                                CoutH + (size_t)(mr0 + 8) * CPAD + n) = h1;
                        } else {
                            float2 r0 = *reinterpret_cast<const float2*>(
                                resid + (size_t)mr0 * CPAD + n);
                            float2 r1 = *reinterpret_cast<const float2*>(
                                resid + (size_t)(mr0 + 8) * CPAD + n);
                            float2 v0 = make_float2(r0.x + 0.5f * c0,
                                                    r0.y + 0.5f * c1);
                            float2 v1 = make_float2(r1.x + 0.5f * c2,
                                                    r1.y + 0.5f * c3);
                            *reinterpret_cast<float2*>(
                                CoutF + (size_t)mr0 * C_DIM + n) = v0;
                            *reinterpret_cast<float2*>(
                                CoutF + (size_t)(mr0 + 8) * C_DIM + n) = v1;
                        }
                    }
                }
            }
#pragma unroll
            for (int i = 0; i < 4; i++)
#pragma unroll
                for (int j = 0; j < 8; j++)
#pragma unroll
                    for (int c = 0; c < 4; c++) acc[i][j][c] = 0.f;
        }
    }
}

// ---------------------------------------------------------------------------
// Host: tensormap encode via dlopen (no -lcuda link dependency)
// ---------------------------------------------------------------------------
typedef CUresult (*PFN_encodeTiled)(
    CUtensorMap*, CUtensorMapDataType, cuuint32_t, void*,
    const cuuint64_t*, const cuuint64_t*, const cuuint32_t*, const cuuint32_t*,
    CUtensorMapInterleave, CUtensorMapSwizzle, CUtensorMapL2promotion,
    CUtensorMapFloatOOBfill);

static PFN_encodeTiled get_encoder() {
    static PFN_encodeTiled fn = nullptr;
    static bool tried = false;
    if (!tried) {
        tried = true;
        void* h = dlopen("libcuda.so.1", RTLD_NOW | RTLD_GLOBAL);
        if (!h) h = dlopen("libcuda.so", RTLD_NOW | RTLD_GLOBAL);
        if (h) fn = (PFN_encodeTiled)dlsym(h, "cuTensorMapEncodeTiled");
    }
    return fn;
}

static bool make_map(CUtensorMap* m, PFN_encodeTiled enc, void* base,
                     unsigned long long rows) {
    cuuint64_t dims[2]    = {(cuuint64_t)CPAD, (cuuint64_t)rows};
    cuuint64_t strides[1] = {(cuuint64_t)CPAD * 2};
    cuuint32_t box[2]     = {BK, BM};      // 64 fp16 (=128B) x 128 rows
    cuuint32_t es[2]      = {1, 1};
    return enc(m, CU_TENSOR_MAP_DATA_TYPE_UINT16, 2, base, dims, strides, box,
               es, CU_TENSOR_MAP_INTERLEAVE_NONE, CU_TENSOR_MAP_SWIZZLE_128B,
               CU_TENSOR_MAP_L2_PROMOTION_L2_128B,
               CU_TENSOR_MAP_FLOAT_OOB_FILL_NONE) == CUDA_SUCCESS;
}

// ---------------------------------------------------------------------------
// Launch: inputs per metadata order: x, adj, Wp, bp, hw1, hw2
// ---------------------------------------------------------------------------
extern "C" void kernel_launch(void* const* d_in, const int* in_sizes, int n_in,
                              void* d_out, int out_size) {
    const float* x   = (const float*)d_in[0];
    const float* adj = (const float*)d_in[1];
    const float* Wp  = (const float*)d_in[2];
    const float* bp  = (const float*)d_in[3];
    const float* hw1 = (const float*)d_in[4];
    const float* hw2 = (const float*)d_in[5];
    float* out = (float*)d_out;

    __half *p_xh, *p_wph, *p_adj1, *p_adj2, *p_xinit_h, *p_out1_h;
    float *p_xinit_f;
    cudaGetSymbolAddress((void**)&p_xh,      g_xh);
    cudaGetSymbolAddress((void**)&p_wph,     g_wph);
    cudaGetSymbolAddress((void**)&p_adj1,    g_adj1);
    cudaGetSymbolAddress((void**)&p_adj2,    g_adj2);
    cudaGetSymbolAddress((void**)&p_xinit_h, g_xinit_h);
    cudaGetSymbolAddress((void**)&p_xinit_f, g_xinit_f);
    cudaGetSymbolAddress((void**)&p_out1_h,  g_out1_h);

    PFN_encodeTiled enc = get_encoder();
    if (!enc) return;   // no driver symbol: fail loudly (0-node graph)

    CUtensorMap mA0, mA1, mA2, mB0, mB1, mB2;
    bool ok = true;
    ok &= make_map(&mA0, enc, p_xh,      B_DIM);
    ok &= make_map(&mA1, enc, p_xinit_h, B_DIM);
    ok &= make_map(&mA2, enc, p_out1_h,  B_DIM);
    ok &= make_map(&mB0, enc, p_wph,     C_DIM);
    ok &= make_map(&mB1, enc, p_adj1,    C_DIM);
    ok &= make_map(&mB2, enc, p_adj2,    C_DIM);
    if (!ok) return;

    cudaFuncSetAttribute(gemm_tc<0>,
        cudaFuncAttributeMaxDynamicSharedMemorySize, SMEM_BYTES);
    cudaFuncSetAttribute(gemm_tc<1>,
        cudaFuncAttributeMaxDynamicSharedMemorySize, SMEM_BYTES);
    cudaFuncSetAttribute(gemm_tc<2>,
        cudaFuncAttributeMaxDynamicSharedMemorySize, SMEM_BYTES);

    // prep: convert x, Wp to fp16; prescale adj by head means -> fp16
    {
        int n4 = (B_DIM * D_DIM) / 4;
        conv_half_kernel<<<(n4 + 255) / 256, 256>>>(x, p_xh, n4);
        int w4 = (C_DIM * D_DIM) / 4;
        conv_half_kernel<<<(w4 + 255) / 256, 256>>>(Wp, p_wph, w4);
        dim3 g(CPAD / 256, C_DIM);
        prep_adj_kernel<<<g, 256>>>(adj, hw1, hw2);
    }

    dim3 grid(GRID);
    dim3 block(NTH);

    gemm_tc<0><<<grid, block, SMEM_BYTES>>>(mA0, mB0, bp, nullptr,
                                            p_xinit_f, p_xinit_h);
    gemm_tc<1><<<grid, block, SMEM_BYTES>>>(mA1, mB1, nullptr, nullptr,
                                            nullptr, p_out1_h);
    gemm_tc<2><<<grid, block, SMEM_BYTES>>>(mA2, mB2, nullptr, p_xinit_f,
                                            out, nullptr);
}

// round 15
// speedup vs baseline: 1.1174x; 1.1174x over previous
#include <cuda_runtime.h>
#include <cuda_fp16.h>
#include <cuda.h>
#include <dlfcn.h>
#include <cstdint>
#include <cstddef>

// ---------------------------------------------------------------------------
// Problem dims (fixed by the dataset)
// ---------------------------------------------------------------------------
#define B_DIM 16384
#define C_DIM 1000
#define D_DIM 1024
#define CPAD  1024   // padded K / leading dim everywhere

// GEMM tiling (fp16 m16n8k16): 128x128x64 CTA tile, 4 warps of 64x64, occ 2
#define BM 128
#define BN 128
#define BK 64              // fp16 elements per k-tile = 128 B per row
#define KT (CPAD / BK)     // 16
#define STAGES 3
#define NTH 128

#define A_TILE_BYTES (BM * 128)                 // 16384 (swizzled 128B rows)
#define B_TILE_BYTES (BN * 128)                 // 16384
#define STAGE_BYTES (A_TILE_BYTES + B_TILE_BYTES)   // 32768
#define TX_BYTES STAGE_BYTES                    // exact TMA bytes per stage
#define SMEM_BYTES (STAGES * STAGE_BYTES + 1024)    // +align slack -> 2 CTAs/SM

// ---------------------------------------------------------------------------
// Device scratch (no allocation allowed). Zero-initialized at load.
// ---------------------------------------------------------------------------
__device__ __half g_xh   [(size_t)B_DIM * CPAD];   // fp16(x)
__device__ __half g_wph  [(size_t)C_DIM * CPAD];   // fp16(Wp)
__device__ __half g_adj1 [(size_t)C_DIM * CPAD];   // fp16(adj*w1)
__device__ __half g_adj2 [(size_t)C_DIM * CPAD];
__device__ __half g_xinit_h[(size_t)B_DIM * CPAD]; // fp16(x@Wp^T+bp)
__device__ float  g_xinit_f[(size_t)B_DIM * CPAD]; // f32 copy for residual
__device__ __half g_out1_h [(size_t)B_DIM * CPAD]; // fp16(relu(gcn1))

// ---------------------------------------------------------------------------
// PTX helpers (sm_80/sm_90 base features only — legal for plain sm_100)
// ---------------------------------------------------------------------------
__device__ __forceinline__ uint32_t su32(const void* p) {
    uint32_t a;
    asm("{ .reg .u64 t; cvta.to.shared.u64 t, %1; cvt.u32.u64 %0, t; }"
        : "=r"(a) : "l"(p));
    return a;
}

#define MBAR_INIT(addr, cnt) \
    asm volatile("mbarrier.init.shared.b64 [%0], %1;" \
                 :: "r"(addr), "r"((uint32_t)(cnt)) : "memory")
#define MBAR_EXPECT(addr, bytes) \
    asm volatile("mbarrier.arrive.expect_tx.shared::cta.b64 _, [%0], %1;" \
                 :: "r"(addr), "r"((uint32_t)(bytes)) : "memory")

__device__ __forceinline__ void mbar_wait(uint32_t mbar, uint32_t parity) {
    uint32_t done;
    asm volatile(
        "{ .reg .pred p;\n"
        "  mbarrier.try_wait.parity.acquire.cta.shared::cta.b64 p, [%1], %2;\n"
        "  selp.b32 %0, 1, 0, p; }"
        : "=r"(done) : "r"(mbar), "r"(parity) : "memory");
    if (!done) {
        asm volatile(
            "{ .reg .pred P1;\n"
            "WAIT_LOOP_%=:\n"
            "  mbarrier.try_wait.parity.acquire.cta.shared::cta.b64 P1, [%0], %1, 0x989680;\n"
            "  @P1 bra.uni WAIT_DONE_%=;\n"
            "  bra.uni WAIT_LOOP_%=;\n"
            "WAIT_DONE_%=:\n}"
            :: "r"(mbar), "r"(parity) : "memory");
    }
}

__device__ __forceinline__ void tma2d(uint32_t dst, const void* map,
                                      int x, int y, uint32_t mbar) {
    asm volatile(
        "cp.async.bulk.tensor.2d.shared::cta.global.tile.mbarrier::complete_tx::bytes "
        "[%0], [%1, {%2, %3}], [%4];"
        :: "r"(dst), "l"(map), "r"(x), "r"(y), "r"(mbar) : "memory");
}

__device__ __forceinline__ void ldsm4(uint32_t* r, uint32_t addr) {
    asm volatile("ldmatrix.sync.aligned.m8n8.x4.shared.b16 {%0,%1,%2,%3}, [%4];"
                 : "=r"(r[0]), "=r"(r[1]), "=r"(r[2]), "=r"(r[3])
                 : "r"(addr));
}

__device__ __forceinline__ void mma16816(float* c, const uint32_t* a,
                                         uint32_t b0, uint32_t b1) {
    asm volatile(
        "mma.sync.aligned.m16n8k16.row.col.f32.f16.f16.f32 "
        "{%0,%1,%2,%3}, {%4,%5,%6,%7}, {%8,%9}, {%0,%1,%2,%3};\n"
        : "+f"(c[0]), "+f"(c[1]), "+f"(c[2]), "+f"(c[3])
        : "r"(a[0]), "r"(a[1]), "r"(a[2]), "r"(a[3]), "r"(b0), "r"(b1));
}

// ---------------------------------------------------------------------------
// Prep kernels
// ---------------------------------------------------------------------------
__global__ void conv_half_kernel(const float* __restrict__ src,
                                 __half* __restrict__ dst, int n4) {
    int i = blockIdx.x * blockDim.x + threadIdx.x;
    if (i < n4) {
        float4 v = reinterpret_cast<const float4*>(src)[i];
        __half2 h0 = __floats2half2_rn(v.x, v.y);
        __half2 h1 = __floats2half2_rn(v.z, v.w);
        uint2 u;
        u.x = *reinterpret_cast<uint32_t*>(&h0);
        u.y = *reinterpret_cast<uint32_t*>(&h1);
        reinterpret_cast<uint2*>(dst)[i] = u;
    }
}

__global__ void prep_adj_kernel(const float* __restrict__ adj,
                                const float* __restrict__ hw1,
                                const float* __restrict__ hw2) {
    int k = blockIdx.x * blockDim.x + threadIdx.x;   // 0..1023
    int c = blockIdx.y;                              // 0..999
    float a1 = 0.f, a2 = 0.f;
    if (k < C_DIM) {
        float av = adj[(size_t)c * C_DIM + k];
        float w1 = (hw1[k] + hw1[C_DIM + k] + hw1[2 * C_DIM + k]) * (1.f / 3.f);
        float w2 = (hw2[k] + hw2[C_DIM + k] + hw2[2 * C_DIM + k]) * (1.f / 3.f);
        a1 = av * w1;
        a2 = av * w2;
    }
    g_adj1[(size_t)c * CPAD + k] = __float2half_rn(a1);
    g_adj2[(size_t)c * CPAD + k] = __float2half_rn(a2);
}

// ---------------------------------------------------------------------------
// Fused fp16 mma.sync GEMM, TMA front-end (R12 sync scheme) + B-frag
// double-buffering (128x128x64 tiles, 64x64 warp tiles, 4 warps, occ 2)
//   MODE 0: +bias -> fp16 CoutH AND f32 CoutF       (ld CPAD)
//   MODE 1: relu  -> fp16 CoutH                     (ld CPAD)
//   MODE 2: CoutF = resid + 0.5*acc                 (ld C_DIM, final output)
// TMA SW128 layout == granule c of row r at ((c ^ (r&7)) * 16).
// ---------------------------------------------------------------------------
template <int MODE>
__global__ void __launch_bounds__(NTH, 2)
gemm_tc(const __grid_constant__ CUtensorMap tmA,
        const __grid_constant__ CUtensorMap tmB,
        const float* __restrict__ bias, const float* __restrict__ resid,
        float* __restrict__ CoutF, __half* __restrict__ CoutH)
{
    extern __shared__ char smem[];
    const uint32_t sraw = su32(smem);
    const uint32_t sm0 = (sraw + 1023u) & ~1023u;   // 1024-align for SW128
    __shared__ __align__(8) uint64_t mbar_s[STAGES];
    const uint32_t mb0 = su32(mbar_s);

    const int tid  = threadIdx.x;
    const int warp = tid >> 5;
    const int lane = tid & 31;
    const int g = lane >> 2;          // groupID 0..7
    const int t = lane & 3;           // thread-in-group 0..3
    const int wm = (warp >> 1) * 64;  // warp M offset (0 or 64)
    const int wn = (warp & 1) * 64;   // warp N offset (0 or 64)

    const int m0 = blockIdx.y * BM;
    const int n0 = blockIdx.x * BN;

    if (tid == 0) {
#pragma unroll
        for (int s = 0; s < STAGES; s++) MBAR_INIT(mb0 + 8u * s, 1);
    }
    __syncthreads();

    // prologue: issue loads for kt = 0 .. STAGES-2
    if (tid == 0) {
#pragma unroll
        for (int kt = 0; kt < STAGES - 1; kt++) {
            const uint32_t mb = mb0 + 8u * kt;
            MBAR_EXPECT(mb, TX_BYTES);            // exactly A+B tile bytes
            tma2d(sm0 + kt * STAGE_BYTES, &tmA, kt * BK, m0, mb);
            tma2d(sm0 + kt * STAGE_BYTES + A_TILE_BYTES, &tmB, kt * BK, n0, mb);
        }
    }

    // ldmatrix per-thread row addressing: matrix id = lane>>3, row = lane&7.
    const int mi  = lane >> 3;
    const int rid = lane & 7;
    const int aRow = wm + (mi & 1) * 8 + rid;       // + i*16
    const int aKh  = mi >> 1;                       // k-half within k16
    const int bRow = wn + (mi >> 1) * 8 + rid;      // + jj*16
    const int bKh  = mi & 1;

    float acc[4][8][4];
#pragma unroll
    for (int i = 0; i < 4; i++)
#pragma unroll
        for (int j = 0; j < 8; j++)
#pragma unroll
            for (int c = 0; c < 4; c++) acc[i][j][c] = 0.f;

    for (int kt = 0; kt < KT; kt++) {
        const int slot = kt % STAGES;
        mbar_wait(mb0 + 8u * slot, (uint32_t)((kt / STAGES) & 1));
        __syncthreads();   // all warps done reading slot (kt+2)%3 from kt-1

        const int kn = kt + STAGES - 1;
        if (kn < KT && tid == 0) {
            const int sl = kn % STAGES;
            const uint32_t mb = mb0 + 8u * sl;
            MBAR_EXPECT(mb, TX_BYTES);
            tma2d(sm0 + sl * STAGE_BYTES, &tmA, kn * BK, m0, mb);
            tma2d(sm0 + sl * STAGE_BYTES + A_TILE_BYTES, &tmB, kn * BK, n0, mb);
        }

        const uint32_t sA = sm0 + slot * STAGE_BYTES;
        const uint32_t sB = sA + A_TILE_BYTES;

        // B fragments double-buffered across ks; A loaded per ks.
        uint32_t b[2][4][4];
#pragma unroll
        for (int jj = 0; jj < 4; jj++) {            // ks=0 B frags
            const int r = bRow + jj * 16;
            ldsm4(b[0][jj], sB + (uint32_t)(r * 128 + ((bKh ^ (r & 7)) << 4)));
        }

#pragma unroll
        for (int ks = 0; ks < 4; ks++) {           // 4 x k16 steps per 64-k tile
            const int cur = ks & 1, nxt = cur ^ 1;
            const int ga = 2 * ks + aKh;           // A swizzle granule
            uint32_t a[4][4];
#pragma unroll
            for (int i = 0; i < 4; i++) {
                const int r = aRow + i * 16;
                ldsm4(a[i], sA + (uint32_t)(r * 128 + ((ga ^ (r & 7)) << 4)));
            }
            if (ks < 3) {                          // prefetch next B under MMAs
                const int gb = 2 * (ks + 1) + bKh;
#pragma unroll
                for (int jj = 0; jj < 4; jj++) {
                    const int r = bRow + jj * 16;
                    ldsm4(b[nxt][jj],
                          sB + (uint32_t)(r * 128 + ((gb ^ (r & 7)) << 4)));
                }
            }
            // b[x][jj] regs: [n8(2jj) lo][n8(2jj) hi][n8(2jj+1) lo][n8(2jj+1) hi]
#pragma unroll
            for (int i = 0; i < 4; i++)
#pragma unroll
                for (int j = 0; j < 8; j++)
                    mma16816(acc[i][j], a[i],
                             b[cur][j >> 1][(j & 1) * 2],
                             b[cur][j >> 1][(j & 1) * 2 + 1]);
        }
    }

    // epilogue
#pragma unroll
    for (int i = 0; i < 4; i++) {
        const int mr0 = m0 + wm + i * 16 + g;       // rows mr0 and mr0+8
#pragma unroll
        for (int j = 0; j < 8; j++) {
            const int n = n0 + wn + j * 8 + t * 2;
            if (n < C_DIM) {
                float c0 = acc[i][j][0], c1 = acc[i][j][1];
                float c2 = acc[i][j][2], c3 = acc[i][j][3];
                if (MODE == 0) {
                    const float b0 = bias[n], b1 = bias[n + 1];
                    c0 += b0; c1 += b1; c2 += b0; c3 += b1;
                    __half2 h0 = __floats2half2_rn(c0, c1);
                    __half2 h1 = __floats2half2_rn(c2, c3);
                    *reinterpret_cast<__half2*>(
                        CoutH + (size_t)mr0 * CPAD + n) = h0;
                    *reinterpret_cast<__half2*>(
                        CoutH + (size_t)(mr0 + 8) * CPAD + n) = h1;
                    *reinterpret_cast<float2*>(
                        CoutF + (size_t)mr0 * CPAD + n) = make_float2(c0, c1);
                    *reinterpret_cast<float2*>(
                        CoutF + (size_t)(mr0 + 8) * CPAD + n) = make_float2(c2, c3);
                } else if (MODE == 1) {
                    c0 = fmaxf(c0, 0.f); c1 = fmaxf(c1, 0.f);
                    c2 = fmaxf(c2, 0.f); c3 = fmaxf(c3, 0.f);
                    __half2 h0 = __floats2half2_rn(c0, c1);
                    __half2 h1 = __floats2half2_rn(c2, c3);
                    *reinterpret_cast<__half2*>(
                        CoutH + (size_t)mr0 * CPAD + n) = h0;
                    *reinterpret_cast<__half2*>(
                        CoutH + (size_t)(mr0 + 8) * CPAD + n) = h1;
                } else {
                    float2 r0 = *reinterpret_cast<const float2*>(
                        resid + (size_t)mr0 * CPAD + n);
                    float2 r1 = *reinterpret_cast<const float2*>(
                        resid + (size_t)(mr0 + 8) * CPAD + n);
                    float2 v0 = make_float2(r0.x + 0.5f * c0, r0.y + 0.5f * c1);
                    float2 v1 = make_float2(r1.x + 0.5f * c2, r1.y + 0.5f * c3);
                    *reinterpret_cast<float2*>(
                        CoutF + (size_t)mr0 * C_DIM + n) = v0;
                    *reinterpret_cast<float2*>(
                        CoutF + (size_t)(mr0 + 8) * C_DIM + n) = v1;
                }
            }
        }
    }
}

// ---------------------------------------------------------------------------
// Host: tensormap encode via dlopen (no -lcuda link dependency)
// ---------------------------------------------------------------------------
typedef CUresult (*PFN_encodeTiled)(
    CUtensorMap*, CUtensorMapDataType, cuuint32_t, void*,
    const cuuint64_t*, const cuuint64_t*, const cuuint32_t*, const cuuint32_t*,
    CUtensorMapInterleave, CUtensorMapSwizzle, CUtensorMapL2promotion,
    CUtensorMapFloatOOBfill);

static PFN_encodeTiled get_encoder() {
    static PFN_encodeTiled fn = nullptr;
    static bool tried = false;
    if (!tried) {
        tried = true;
        void* h = dlopen("libcuda.so.1", RTLD_NOW | RTLD_GLOBAL);
        if (!h) h = dlopen("libcuda.so", RTLD_NOW | RTLD_GLOBAL);
        if (h) fn = (PFN_encodeTiled)dlsym(h, "cuTensorMapEncodeTiled");
    }
    return fn;
}

static bool make_map(CUtensorMap* m, PFN_encodeTiled enc, void* base,
                     unsigned long long rows) {
    cuuint64_t dims[2]    = {(cuuint64_t)CPAD, (cuuint64_t)rows};
    cuuint64_t strides[1] = {(cuuint64_t)CPAD * 2};
    cuuint32_t box[2]     = {BK, BM};      // 64 fp16 (=128B) x 128 rows
    cuuint32_t es[2]      = {1, 1};
    return enc(m, CU_TENSOR_MAP_DATA_TYPE_UINT16, 2, base, dims, strides, box,
               es, CU_TENSOR_MAP_INTERLEAVE_NONE, CU_TENSOR_MAP_SWIZZLE_128B,
               CU_TENSOR_MAP_L2_PROMOTION_L2_128B,
               CU_TENSOR_MAP_FLOAT_OOB_FILL_NONE) == CUDA_SUCCESS;
}

// ---------------------------------------------------------------------------
// Launch: inputs per metadata order: x, adj, Wp, bp, hw1, hw2
// ---------------------------------------------------------------------------
extern "C" void kernel_launch(void* const* d_in, const int* in_sizes, int n_in,
                              void* d_out, int out_size) {
    const float* x   = (const float*)d_in[0];
    const float* adj = (const float*)d_in[1];
    const float* Wp  = (const float*)d_in[2];
    const float* bp  = (const float*)d_in[3];
    const float* hw1 = (const float*)d_in[4];
    const float* hw2 = (const float*)d_in[5];
    float* out = (float*)d_out;

    __half *p_xh, *p_wph, *p_adj1, *p_adj2, *p_xinit_h, *p_out1_h;
    float *p_xinit_f;
    cudaGetSymbolAddress((void**)&p_xh,      g_xh);
    cudaGetSymbolAddress((void**)&p_wph,     g_wph);
    cudaGetSymbolAddress((void**)&p_adj1,    g_adj1);
    cudaGetSymbolAddress((void**)&p_adj2,    g_adj2);
    cudaGetSymbolAddress((void**)&p_xinit_h, g_xinit_h);
    cudaGetSymbolAddress((void**)&p_xinit_f, g_xinit_f);
    cudaGetSymbolAddress((void**)&p_out1_h,  g_out1_h);

    PFN_encodeTiled enc = get_encoder();
    if (!enc) return;   // no driver symbol: fail loudly (0-node graph)

    CUtensorMap mA0, mA1, mA2, mB0, mB1, mB2;
    bool ok = true;
    ok &= make_map(&mA0, enc, p_xh,      B_DIM);
    ok &= make_map(&mA1, enc, p_xinit_h, B_DIM);
    ok &= make_map(&mA2, enc, p_out1_h,  B_DIM);
    ok &= make_map(&mB0, enc, p_wph,     C_DIM);
    ok &= make_map(&mB1, enc, p_adj1,    C_DIM);
    ok &= make_map(&mB2, enc, p_adj2,    C_DIM);
    if (!ok) return;

    cudaFuncSetAttribute(gemm_tc<0>,
        cudaFuncAttributeMaxDynamicSharedMemorySize, SMEM_BYTES);
    cudaFuncSetAttribute(gemm_tc<1>,
        cudaFuncAttributeMaxDynamicSharedMemorySize, SMEM_BYTES);
    cudaFuncSetAttribute(gemm_tc<2>,
        cudaFuncAttributeMaxDynamicSharedMemorySize, SMEM_BYTES);

    // prep: convert x, Wp to fp16; prescale adj by head means -> fp16
    {
        int n4 = (B_DIM * D_DIM) / 4;
        conv_half_kernel<<<(n4 + 255) / 256, 256>>>(x, p_xh, n4);
        int w4 = (C_DIM * D_DIM) / 4;
        conv_half_kernel<<<(w4 + 255) / 256, 256>>>(Wp, p_wph, w4);
        dim3 g(CPAD / 256, C_DIM);
        prep_adj_kernel<<<g, 256>>>(adj, hw1, hw2);
    }

    dim3 grid((C_DIM + BN - 1) / BN, B_DIM / BM);  // (8, 128)
    dim3 block(NTH);

    gemm_tc<0><<<grid, block, SMEM_BYTES>>>(mA0, mB0, bp, nullptr,
                                            p_xinit_f, p_xinit_h);
    gemm_tc<1><<<grid, block, SMEM_BYTES>>>(mA1, mB1, nullptr, nullptr,
                                            nullptr, p_out1_h);
    gemm_tc<2><<<grid, block, SMEM_BYTES>>>(mA2, mB2, nullptr, p_xinit_f,
                                            out, nullptr);
}